// round 1
// baseline (speedup 1.0000x reference)
#include <cuda_runtime.h>
#include <cuda_bf16.h>

// Problem constants
#define BB 16
#define RR 1024
#define TT 512
#define DD 1024
#define HH 1024

// Scratch (allocation-free rule: __device__ globals)
__device__ float g_Qp[BB * TT * HH];        // 32 MB: Q projection
__device__ float g_W2[BB * 2 * TT * DD];    // 64 MB: per batch rows [0,512)=U, [512,1024)=Y*Ws3
__device__ float g_P [BB * RR * 2 * TT];    // 64 MB: per batch [R,1024]: cols [0,512)=S-c, [512,1024)=G
__device__ float g_c[BB * TT];
__device__ float g_z[BB * TT];
__device__ float g_base[BB * RR];

#define BM 128
#define BN 128
#define BK 16

// Generic fp32 tiled GEMM: C[m,n] = sum_k A[m,k] * B(k,n) (+bias[n])
// TB=false: B row-major [K,N]; TB=true: B row-major [N,K] (NT).
// All dims assumed multiples of tile sizes (true for this problem).
template <bool TB>
__global__ __launch_bounds__(256) void gemm_tile(
    const float* __restrict__ A, const float* __restrict__ B,
    float* __restrict__ C, const float* __restrict__ bias,
    int lda, long long sA, int ldb, long long sB, int ldc, long long sC, int K)
{
    __shared__ float As[BK][BM];
    __shared__ float Bs[BK][BN + 4];

    const int bz = blockIdx.z;
    A += (long long)bz * sA;
    B += (long long)bz * sB;
    C += (long long)bz * sC;

    const int m0 = blockIdx.y * BM;
    const int n0 = blockIdx.x * BN;
    const int tid = threadIdx.x;
    const int tx = tid & 15;   // 16 thread cols
    const int ty = tid >> 4;   // 16 thread rows

    float acc[8][8] = {};
    float ar[8], brf[8];

    for (int k0 = 0; k0 < K; k0 += BK) {
        // A tile 128x16 -> As[k][m] (transposed)
        {
            int t = tid;
            #pragma unroll
            for (int l = 0; l < 2; l++, t += 256) {
                int row = t >> 2;
                int cg  = t & 3;
                float4 v = *reinterpret_cast<const float4*>(
                    &A[(long long)(m0 + row) * lda + k0 + cg * 4]);
                As[cg * 4 + 0][row] = v.x;
                As[cg * 4 + 1][row] = v.y;
                As[cg * 4 + 2][row] = v.z;
                As[cg * 4 + 3][row] = v.w;
            }
        }
        if (TB) {
            int t = tid;
            #pragma unroll
            for (int l = 0; l < 2; l++, t += 256) {
                int row = t >> 2;
                int cg  = t & 3;
                float4 v = *reinterpret_cast<const float4*>(
                    &B[(long long)(n0 + row) * ldb + k0 + cg * 4]);
                Bs[cg * 4 + 0][row] = v.x;
                Bs[cg * 4 + 1][row] = v.y;
                Bs[cg * 4 + 2][row] = v.z;
                Bs[cg * 4 + 3][row] = v.w;
            }
        } else {
            int t = tid;
            #pragma unroll
            for (int l = 0; l < 2; l++, t += 256) {
                int row = t >> 5;
                int cg  = t & 31;
                float4 v = *reinterpret_cast<const float4*>(
                    &B[(long long)(k0 + row) * ldb + n0 + cg * 4]);
                Bs[row][cg * 4 + 0] = v.x;
                Bs[row][cg * 4 + 1] = v.y;
                Bs[row][cg * 4 + 2] = v.z;
                Bs[row][cg * 4 + 3] = v.w;
            }
        }
        __syncthreads();

        #pragma unroll
        for (int k = 0; k < BK; k++) {
            #pragma unroll
            for (int i = 0; i < 8; i++) ar[i] = As[k][ty * 8 + i];
            #pragma unroll
            for (int j = 0; j < 8; j++) brf[j] = Bs[k][tx * 8 + j];
            #pragma unroll
            for (int i = 0; i < 8; i++)
                #pragma unroll
                for (int j = 0; j < 8; j++)
                    acc[i][j] = fmaf(ar[i], brf[j], acc[i][j]);
        }
        __syncthreads();
    }

    #pragma unroll
    for (int i = 0; i < 8; i++) {
        int m = m0 + ty * 8 + i;
        #pragma unroll
        for (int j = 0; j < 8; j += 4) {
            int n = n0 + tx * 8 + j;
            float4 v = make_float4(acc[i][j], acc[i][j + 1], acc[i][j + 2], acc[i][j + 3]);
            if (bias) { v.x += bias[n]; v.y += bias[n + 1]; v.z += bias[n + 2]; v.w += bias[n + 3]; }
            *reinterpret_cast<float4*>(&C[(long long)m * ldc + n]) = v;
        }
    }
}

// out[row] = dot(A[row,:K], v) + (addp ? *addp : 0). One warp per row, 8 rows/block.
__global__ __launch_bounds__(256) void rowdot_kernel(
    const float* __restrict__ A, const float* __restrict__ v,
    const float* __restrict__ addp, float* __restrict__ out, int K)
{
    int row = blockIdx.x * 8 + (threadIdx.x >> 5);
    int lane = threadIdx.x & 31;
    const float* a = A + (long long)row * K;
    float s = 0.f;
    for (int i = lane * 4; i < K; i += 128) {
        float4 x = *reinterpret_cast<const float4*>(&a[i]);
        float4 w = *reinterpret_cast<const float4*>(&v[i]);
        s += x.x * w.x + x.y * w.y + x.z * w.z + x.w * w.w;
    }
    #pragma unroll
    for (int o = 16; o; o >>= 1) s += __shfl_xor_sync(0xffffffffu, s, o);
    if (lane == 0) out[row] = s + (addp ? addp[0] : 0.f);
}

// W2[b, 512+t, d] = Y[b,t,d] * ws3[d]   (float4 granularity)
__global__ __launch_bounds__(256) void yw_kernel(
    const float* __restrict__ Y, const float* __restrict__ ws3, float* __restrict__ W2)
{
    int idx4 = blockIdx.x * blockDim.x + threadIdx.x;   // [0, 16*512*1024/4)
    int d4 = idx4 & 255;                                // 1024/4
    int b  = idx4 >> 17;                                // 512*1024/4 = 131072
    const float4 y = reinterpret_cast<const float4*>(Y)[idx4];
    const float4 w = reinterpret_cast<const float4*>(ws3)[d4];
    float4 r = make_float4(y.x * w.x, y.y * w.y, y.z * w.z, y.w * w.w);
    reinterpret_cast<float4*>(W2)[idx4 + (b + 1) * 131072] = r;
}

// Per (b,r): softmax over S row (512) and weighted reduce with (z + G).
__global__ __launch_bounds__(256) void softmax_out_kernel(
    const float* __restrict__ P, const float* __restrict__ c,
    const float* __restrict__ z, const float* __restrict__ base,
    float* __restrict__ out)
{
    const int b = blockIdx.y, r = blockIdx.x;
    const float* Prow = P + ((long long)b * RR + r) * (2 * TT);
    const float* cb = c + b * TT;
    const float* zb = z + b * TT;
    const int t = threadIdx.x;
    const int lane = t & 31, wid = t >> 5;

    float s0 = Prow[t]       + cb[t];
    float s1 = Prow[t + 256] + cb[t + 256];
    float g0 = Prow[512 + t];
    float g1 = Prow[768 + t];

    __shared__ float sm[8], smp[8], smw[8];

    float m = fmaxf(s0, s1);
    #pragma unroll
    for (int o = 16; o; o >>= 1) m = fmaxf(m, __shfl_xor_sync(0xffffffffu, m, o));
    if (lane == 0) sm[wid] = m;
    __syncthreads();
    if (wid == 0) {
        float v = sm[lane & 7];
        #pragma unroll
        for (int o = 4; o; o >>= 1) v = fmaxf(v, __shfl_xor_sync(0xffffffffu, v, o));
        if (lane == 0) sm[0] = v;
    }
    __syncthreads();
    m = sm[0];

    float p0 = expf(s0 - m), p1 = expf(s1 - m);
    float ps = p0 + p1;
    float ws = p0 * (zb[t] + g0) + p1 * (zb[t + 256] + g1);
    #pragma unroll
    for (int o = 16; o; o >>= 1) {
        ps += __shfl_xor_sync(0xffffffffu, ps, o);
        ws += __shfl_xor_sync(0xffffffffu, ws, o);
    }
    if (lane == 0) { smp[wid] = ps; smw[wid] = ws; }
    __syncthreads();
    if (t == 0) {
        float tp = 0.f, tw = 0.f;
        #pragma unroll
        for (int i = 0; i < 8; i++) { tp += smp[i]; tw += smw[i]; }
        out[b * RR + r] = base[b * RR + r] + tw / tp;
    }
}

extern "C" void kernel_launch(void* const* d_in, const int* in_sizes, int n_in,
                              void* d_out, int out_size)
{
    const float* X  = (const float*)d_in[0]; // region_feats [B,R,D]
    const float* Y  = (const float*)d_in[1]; // query_embs   [B,T,D]
    const float* Wr = (const float*)d_in[2]; // [D,H]
    const float* br = (const float*)d_in[3]; // [H]
    const float* Wq = (const float*)d_in[4]; // [D,H]
    const float* bq = (const float*)d_in[5]; // [H]
    const float* Ws = (const float*)d_in[6]; // [3D]
    const float* bs = (const float*)d_in[7]; // [1]
    float* out = (float*)d_out;

    float *Qp, *W2, *P, *cb, *zb, *baseb;
    cudaGetSymbolAddress((void**)&Qp, g_Qp);
    cudaGetSymbolAddress((void**)&W2, g_W2);
    cudaGetSymbolAddress((void**)&P, g_P);
    cudaGetSymbolAddress((void**)&cb, g_c);
    cudaGetSymbolAddress((void**)&zb, g_z);
    cudaGetSymbolAddress((void**)&baseb, g_base);

    // 1) Qp = Y @ Wq + bq : M=B*T=8192, N=1024, K=1024 (NN)
    gemm_tile<false><<<dim3(HH / BN, (BB * TT) / BM, 1), 256>>>(
        Y, Wq, Qp, bq, DD, 0LL, HH, 0LL, HH, 0LL, DD);

    // 2) c[b,t] = Qp[b,t] . br ; z[b,t] = Y[b,t] . Ws2 ; base[b,r] = X[b,r] . Ws1 + bs
    rowdot_kernel<<<(BB * TT) / 8, 256>>>(Qp, br, nullptr, cb, HH);
    rowdot_kernel<<<(BB * TT) / 8, 256>>>(Y, Ws + DD, nullptr, zb, DD);
    rowdot_kernel<<<(BB * RR) / 8, 256>>>(X, Ws, bs, baseb, DD);

    // 3) W2 rows [512,1024): Yw = Y * Ws3
    yw_kernel<<<(BB * TT * DD / 4) / 256, 256>>>(Y, Ws + 2 * DD, W2);

    // 4) W2 rows [0,512): U = Qp @ Wr^T : batched NT, M=512, N=1024, K=1024
    gemm_tile<true><<<dim3(DD / BN, TT / BM, BB), 256>>>(
        Qp, Wr, W2, nullptr,
        HH, (long long)TT * HH, HH, 0LL, DD, (long long)2 * TT * DD, HH);

    // 5) P = X @ W2^T : batched NT, M=1024, N=1024, K=1024 per batch
    gemm_tile<true><<<dim3((2 * TT) / BN, RR / BM, BB), 256>>>(
        X, W2, P, nullptr,
        DD, (long long)RR * DD, DD, (long long)2 * TT * DD,
        2 * TT, (long long)RR * 2 * TT, DD);

    // 6) softmax + fused epilogue
    softmax_out_kernel<<<dim3(RR, BB), 256>>>(P, cb, zb, baseb, out);
}

// round 2
// speedup vs baseline: 1.1269x; 1.1269x over previous
#include <cuda_runtime.h>
#include <cuda_bf16.h>

// Problem constants
#define BB 16
#define RR 1024
#define TT 512
#define DD 1024
#define HH 1024

// Scratch (allocation-free rule: __device__ globals)
__device__ float g_Qp[BB * TT * HH];        // 32 MB: Q projection
__device__ float g_W2[BB * 2 * TT * DD];    // 64 MB: per batch rows [0,512)=U, [512,1024)=Y*Ws3
__device__ float g_P [BB * RR * 2 * TT];    // 64 MB: per batch [R,1024]: cols [0,512)=S-c, [512,1024)=G
__device__ float g_c[BB * TT];
__device__ float g_z[BB * TT];
__device__ float g_base[BB * RR];

#define BM 128
#define BN 128
#define BK 16

// ---- packed f32x2 helpers (sm_100+) ----
__device__ __forceinline__ void fma2(unsigned long long& d, unsigned long long a, unsigned long long b) {
    asm("fma.rn.f32x2 %0, %1, %2, %0;" : "+l"(d) : "l"(a), "l"(b));
}
__device__ __forceinline__ unsigned long long dup2(float x) {
    unsigned long long r; unsigned int xi = __float_as_uint(x);
    asm("mov.b64 %0, {%1, %1};" : "=l"(r) : "r"(xi));
    return r;
}
__device__ __forceinline__ float2 unpk(unsigned long long v) {
    unsigned int lo, hi;
    asm("mov.b64 {%0, %1}, %2;" : "=r"(lo), "=r"(hi) : "l"(v));
    return make_float2(__uint_as_float(lo), __uint_as_float(hi));
}

// Generic fp32 tiled GEMM with packed f32x2 math: C[m,n] = sum_k A[m,k]*B(k,n) (+bias[n])
// TB=false: B row-major [K,N]; TB=true: B row-major [N,K] (NT).
// All dims are multiples of tile sizes for this problem.
template <bool TB>
__global__ __launch_bounds__(256, 2) void gemm_tile(
    const float* __restrict__ A, const float* __restrict__ B,
    float* __restrict__ C, const float* __restrict__ bias,
    int lda, long long sA, int ldb, long long sB, int ldc, long long sC, int K)
{
    __shared__ float As[BK][BM];
    __shared__ float Bs[BK][BN + 4];

    const int bz = blockIdx.z;
    A += (long long)bz * sA;
    B += (long long)bz * sB;
    C += (long long)bz * sC;

    const int m0 = blockIdx.y * BM;
    const int n0 = blockIdx.x * BN;
    const int tid = threadIdx.x;
    const int tx = tid & 15;   // 16 thread cols
    const int ty = tid >> 4;   // 16 thread rows

    // Packed accumulators: rows i (8), col-pairs q (4) -> cols (tx*8+2q, tx*8+2q+1)
    unsigned long long acc[8][4];
    #pragma unroll
    for (int i = 0; i < 8; i++)
        #pragma unroll
        for (int q = 0; q < 4; q++) acc[i][q] = 0ULL;

    // Register-staged prefetch of global tiles
    float4 pa[2], pb[2];

    // indices for the two staged loads per tile
    const int aRow0 = tid >> 2, aCg0 = tid & 3;
    const int aRow1 = (tid + 256) >> 2, aCg1 = (tid + 256) & 3;
    // NN B-load indices
    const int bRowN0 = tid >> 5, bCgN0 = tid & 31;
    const int bRowN1 = (tid + 256) >> 5, bCgN1 = (tid + 256) & 31;

    // initial loads (k0 = 0)
    pa[0] = *reinterpret_cast<const float4*>(&A[(long long)(m0 + aRow0) * lda + aCg0 * 4]);
    pa[1] = *reinterpret_cast<const float4*>(&A[(long long)(m0 + aRow1) * lda + aCg1 * 4]);
    if (TB) {
        pb[0] = *reinterpret_cast<const float4*>(&B[(long long)(n0 + aRow0) * ldb + aCg0 * 4]);
        pb[1] = *reinterpret_cast<const float4*>(&B[(long long)(n0 + aRow1) * ldb + aCg1 * 4]);
    } else {
        pb[0] = *reinterpret_cast<const float4*>(&B[(long long)(bRowN0) * ldb + n0 + bCgN0 * 4]);
        pb[1] = *reinterpret_cast<const float4*>(&B[(long long)(bRowN1) * ldb + n0 + bCgN1 * 4]);
    }

    for (int k0 = 0; k0 < K; k0 += BK) {
        // stage regs -> smem
        As[aCg0 * 4 + 0][aRow0] = pa[0].x;
        As[aCg0 * 4 + 1][aRow0] = pa[0].y;
        As[aCg0 * 4 + 2][aRow0] = pa[0].z;
        As[aCg0 * 4 + 3][aRow0] = pa[0].w;
        As[aCg1 * 4 + 0][aRow1] = pa[1].x;
        As[aCg1 * 4 + 1][aRow1] = pa[1].y;
        As[aCg1 * 4 + 2][aRow1] = pa[1].z;
        As[aCg1 * 4 + 3][aRow1] = pa[1].w;
        if (TB) {
            Bs[aCg0 * 4 + 0][aRow0] = pb[0].x;
            Bs[aCg0 * 4 + 1][aRow0] = pb[0].y;
            Bs[aCg0 * 4 + 2][aRow0] = pb[0].z;
            Bs[aCg0 * 4 + 3][aRow0] = pb[0].w;
            Bs[aCg1 * 4 + 0][aRow1] = pb[1].x;
            Bs[aCg1 * 4 + 1][aRow1] = pb[1].y;
            Bs[aCg1 * 4 + 2][aRow1] = pb[1].z;
            Bs[aCg1 * 4 + 3][aRow1] = pb[1].w;
        } else {
            Bs[bRowN0][bCgN0 * 4 + 0] = pb[0].x;
            Bs[bRowN0][bCgN0 * 4 + 1] = pb[0].y;
            Bs[bRowN0][bCgN0 * 4 + 2] = pb[0].z;
            Bs[bRowN0][bCgN0 * 4 + 3] = pb[0].w;
            Bs[bRowN1][bCgN1 * 4 + 0] = pb[1].x;
            Bs[bRowN1][bCgN1 * 4 + 1] = pb[1].y;
            Bs[bRowN1][bCgN1 * 4 + 2] = pb[1].z;
            Bs[bRowN1][bCgN1 * 4 + 3] = pb[1].w;
        }
        __syncthreads();

        // prefetch next tile into regs (overlaps with compute below)
        const int kn = k0 + BK;
        if (kn < K) {
            pa[0] = *reinterpret_cast<const float4*>(&A[(long long)(m0 + aRow0) * lda + kn + aCg0 * 4]);
            pa[1] = *reinterpret_cast<const float4*>(&A[(long long)(m0 + aRow1) * lda + kn + aCg1 * 4]);
            if (TB) {
                pb[0] = *reinterpret_cast<const float4*>(&B[(long long)(n0 + aRow0) * ldb + kn + aCg0 * 4]);
                pb[1] = *reinterpret_cast<const float4*>(&B[(long long)(n0 + aRow1) * ldb + kn + aCg1 * 4]);
            } else {
                pb[0] = *reinterpret_cast<const float4*>(&B[(long long)(kn + bRowN0) * ldb + n0 + bCgN0 * 4]);
                pb[1] = *reinterpret_cast<const float4*>(&B[(long long)(kn + bRowN1) * ldb + n0 + bCgN1 * 4]);
            }
        }

        // compute: 16 k-steps, packed f32x2 outer product
        #pragma unroll
        for (int k = 0; k < BK; k++) {
            unsigned long long adup[8];
            #pragma unroll
            for (int p = 0; p < 4; p++) {
                float2 av = *reinterpret_cast<const float2*>(&As[k][ty * 8 + 2 * p]);
                adup[2 * p]     = dup2(av.x);
                adup[2 * p + 1] = dup2(av.y);
            }
            unsigned long long b2[4];
            #pragma unroll
            for (int q = 0; q < 4; q++)
                b2[q] = *reinterpret_cast<const unsigned long long*>(&Bs[k][tx * 8 + 2 * q]);
            #pragma unroll
            for (int i = 0; i < 8; i++)
                #pragma unroll
                for (int q = 0; q < 4; q++)
                    fma2(acc[i][q], adup[i], b2[q]);
        }
        __syncthreads();
    }

    #pragma unroll
    for (int i = 0; i < 8; i++) {
        int m = m0 + ty * 8 + i;
        #pragma unroll
        for (int q = 0; q < 4; q += 2) {
            int n = n0 + tx * 8 + 2 * q;
            float2 c0 = unpk(acc[i][q]);
            float2 c1 = unpk(acc[i][q + 1]);
            float4 v = make_float4(c0.x, c0.y, c1.x, c1.y);
            if (bias) { v.x += bias[n]; v.y += bias[n + 1]; v.z += bias[n + 2]; v.w += bias[n + 3]; }
            *reinterpret_cast<float4*>(&C[(long long)m * ldc + n]) = v;
        }
    }
}

// out[row] = dot(A[row,:K], v) + (addp ? *addp : 0). One warp per row, 8 rows/block.
__global__ __launch_bounds__(256) void rowdot_kernel(
    const float* __restrict__ A, const float* __restrict__ v,
    const float* __restrict__ addp, float* __restrict__ out, int K)
{
    int row = blockIdx.x * 8 + (threadIdx.x >> 5);
    int lane = threadIdx.x & 31;
    const float* a = A + (long long)row * K;
    float s = 0.f;
    for (int i = lane * 4; i < K; i += 128) {
        float4 x = *reinterpret_cast<const float4*>(&a[i]);
        float4 w = *reinterpret_cast<const float4*>(&v[i]);
        s += x.x * w.x + x.y * w.y + x.z * w.z + x.w * w.w;
    }
    #pragma unroll
    for (int o = 16; o; o >>= 1) s += __shfl_xor_sync(0xffffffffu, s, o);
    if (lane == 0) out[row] = s + (addp ? addp[0] : 0.f);
}

// W2[b, 512+t, d] = Y[b,t,d] * ws3[d]   (float4 granularity)
__global__ __launch_bounds__(256) void yw_kernel(
    const float* __restrict__ Y, const float* __restrict__ ws3, float* __restrict__ W2)
{
    int idx4 = blockIdx.x * blockDim.x + threadIdx.x;   // [0, 16*512*1024/4)
    int d4 = idx4 & 255;                                // 1024/4
    int b  = idx4 >> 17;                                // 512*1024/4 = 131072
    const float4 y = reinterpret_cast<const float4*>(Y)[idx4];
    const float4 w = reinterpret_cast<const float4*>(ws3)[d4];
    float4 r = make_float4(y.x * w.x, y.y * w.y, y.z * w.z, y.w * w.w);
    reinterpret_cast<float4*>(W2)[idx4 + (b + 1) * 131072] = r;
}

// Per (b,r): softmax over S row (512) and weighted reduce with (z + G).
__global__ __launch_bounds__(256) void softmax_out_kernel(
    const float* __restrict__ P, const float* __restrict__ c,
    const float* __restrict__ z, const float* __restrict__ base,
    float* __restrict__ out)
{
    const int b = blockIdx.y, r = blockIdx.x;
    const float* Prow = P + ((long long)b * RR + r) * (2 * TT);
    const float* cb = c + b * TT;
    const float* zb = z + b * TT;
    const int t = threadIdx.x;
    const int lane = t & 31, wid = t >> 5;

    float s0 = Prow[t]       + cb[t];
    float s1 = Prow[t + 256] + cb[t + 256];
    float g0 = Prow[512 + t];
    float g1 = Prow[768 + t];

    __shared__ float sm[8], smp[8], smw[8];

    float m = fmaxf(s0, s1);
    #pragma unroll
    for (int o = 16; o; o >>= 1) m = fmaxf(m, __shfl_xor_sync(0xffffffffu, m, o));
    if (lane == 0) sm[wid] = m;
    __syncthreads();
    if (wid == 0) {
        float v = sm[lane & 7];
        #pragma unroll
        for (int o = 4; o; o >>= 1) v = fmaxf(v, __shfl_xor_sync(0xffffffffu, v, o));
        if (lane == 0) sm[0] = v;
    }
    __syncthreads();
    m = sm[0];

    float p0 = expf(s0 - m), p1 = expf(s1 - m);
    float ps = p0 + p1;
    float ws = p0 * (zb[t] + g0) + p1 * (zb[t + 256] + g1);
    #pragma unroll
    for (int o = 16; o; o >>= 1) {
        ps += __shfl_xor_sync(0xffffffffu, ps, o);
        ws += __shfl_xor_sync(0xffffffffu, ws, o);
    }
    if (lane == 0) { smp[wid] = ps; smw[wid] = ws; }
    __syncthreads();
    if (t == 0) {
        float tp = 0.f, tw = 0.f;
        #pragma unroll
        for (int i = 0; i < 8; i++) { tp += smp[i]; tw += smw[i]; }
        out[b * RR + r] = base[b * RR + r] + tw / tp;
    }
}

extern "C" void kernel_launch(void* const* d_in, const int* in_sizes, int n_in,
                              void* d_out, int out_size)
{
    const float* X  = (const float*)d_in[0]; // region_feats [B,R,D]
    const float* Y  = (const float*)d_in[1]; // query_embs   [B,T,D]
    const float* Wr = (const float*)d_in[2]; // [D,H]
    const float* br = (const float*)d_in[3]; // [H]
    const float* Wq = (const float*)d_in[4]; // [D,H]
    const float* bq = (const float*)d_in[5]; // [H]
    const float* Ws = (const float*)d_in[6]; // [3D]
    const float* bs = (const float*)d_in[7]; // [1]
    float* out = (float*)d_out;

    float *Qp, *W2, *P, *cb, *zb, *baseb;
    cudaGetSymbolAddress((void**)&Qp, g_Qp);
    cudaGetSymbolAddress((void**)&W2, g_W2);
    cudaGetSymbolAddress((void**)&P, g_P);
    cudaGetSymbolAddress((void**)&cb, g_c);
    cudaGetSymbolAddress((void**)&zb, g_z);
    cudaGetSymbolAddress((void**)&baseb, g_base);

    // 1) Qp = Y @ Wq + bq : M=B*T=8192, N=1024, K=1024 (NN)
    gemm_tile<false><<<dim3(HH / BN, (BB * TT) / BM, 1), 256>>>(
        Y, Wq, Qp, bq, DD, 0LL, HH, 0LL, HH, 0LL, DD);

    // 2) c[b,t] = Qp[b,t] . br ; z[b,t] = Y[b,t] . Ws2 ; base[b,r] = X[b,r] . Ws1 + bs
    rowdot_kernel<<<(BB * TT) / 8, 256>>>(Qp, br, nullptr, cb, HH);
    rowdot_kernel<<<(BB * TT) / 8, 256>>>(Y, Ws + DD, nullptr, zb, DD);
    rowdot_kernel<<<(BB * RR) / 8, 256>>>(X, Ws, bs, baseb, DD);

    // 3) W2 rows [512,1024): Yw = Y * Ws3
    yw_kernel<<<(BB * TT * DD / 4) / 256, 256>>>(Y, Ws + 2 * DD, W2);

    // 4) W2 rows [0,512): U = Qp @ Wr^T : batched NT, M=512, N=1024, K=1024
    gemm_tile<true><<<dim3(DD / BN, TT / BM, BB), 256>>>(
        Qp, Wr, W2, nullptr,
        HH, (long long)TT * HH, HH, 0LL, DD, (long long)2 * TT * DD, HH);

    // 5) P = X @ W2^T : batched NT, M=1024, N=1024, K=1024 per batch
    gemm_tile<true><<<dim3((2 * TT) / BN, RR / BM, BB), 256>>>(
        X, W2, P, nullptr,
        DD, (long long)RR * DD, DD, (long long)2 * TT * DD,
        2 * TT, (long long)RR * 2 * TT, DD);

    // 6) softmax + fused epilogue
    softmax_out_kernel<<<dim3(RR, BB), 256>>>(P, cb, zb, baseb, out);
}

// round 3
// speedup vs baseline: 2.1143x; 1.8763x over previous
#include <cuda_runtime.h>
#include <cuda_bf16.h>
#include <cstdint>

// Problem constants
#define BB 16
#define RR 1024
#define TT 512
#define DD 1024
#define HH 1024

typedef __nv_bfloat16 bf16;

// ---------------- scratch (__device__ globals; no allocation allowed) -------
__device__ float g_Qp[BB * TT * HH];          // 32 MB fp32 Q projection
__device__ float g_P [BB * RR * 2 * TT];      // 64 MB fp32: [b][r][0:512)=S-c, [512:1024)=G
__device__ bf16  g_Xh[BB * RR * DD], g_Xl[BB * RR * DD];      // 32+32 MB
__device__ bf16  g_Yh[BB * TT * DD], g_Yl[BB * TT * DD];      // 16+16 MB
__device__ bf16  g_Qph[BB * TT * HH], g_Qpl[BB * TT * HH];    // 16+16 MB
__device__ bf16  g_WqTh[HH * DD], g_WqTl[HH * DD];            // 2+2 MB ([n=h][k=d])
__device__ bf16  g_Wrh[DD * HH], g_Wrl[DD * HH];              // 2+2 MB ([n=d][k=h])
__device__ bf16  g_W2h[BB * 2 * TT * DD], g_W2l[BB * 2 * TT * DD]; // 32+32 MB
__device__ float g_c[BB * TT];
__device__ float g_z[BB * TT];
__device__ float g_base[BB * RR];

// ---------------- helpers ---------------------------------------------------
__device__ __forceinline__ uint32_t smem_u32(const void* p) {
    return (uint32_t)__cvta_generic_to_shared(p);
}
__device__ __forceinline__ void cp16(void* s, const void* g) {
    asm volatile("cp.async.ca.shared.global [%0], [%1], 16;\n"
                 :: "r"(smem_u32(s)), "l"(g));
}
__device__ __forceinline__ void cp_commit() { asm volatile("cp.async.commit_group;\n"); }
template <int N>
__device__ __forceinline__ void cp_wait() { asm volatile("cp.async.wait_group %0;\n" :: "n"(N)); }

__device__ __forceinline__ void ldm_x4(uint32_t* r, uint32_t addr) {
    asm volatile("ldmatrix.sync.aligned.m8n8.x4.shared.b16 {%0,%1,%2,%3}, [%4];"
                 : "=r"(r[0]), "=r"(r[1]), "=r"(r[2]), "=r"(r[3]) : "r"(addr));
}
__device__ __forceinline__ void mma16816(float* d, const uint32_t* a, const uint32_t* b) {
    asm volatile(
        "mma.sync.aligned.m16n8k16.row.col.f32.bf16.bf16.f32 "
        "{%0,%1,%2,%3},{%4,%5,%6,%7},{%8,%9},{%0,%1,%2,%3};"
        : "+f"(d[0]), "+f"(d[1]), "+f"(d[2]), "+f"(d[3])
        : "r"(a[0]), "r"(a[1]), "r"(a[2]), "r"(a[3]), "r"(b[0]), "r"(b[1]));
}

__device__ __forceinline__ void split1(float v, bf16& h, bf16& l) {
    h = __float2bfloat16(v);
    l = __float2bfloat16(v - __bfloat162float(h));
}
__device__ __forceinline__ uint32_t pk2(bf16 a, bf16 b) {
    return (uint32_t)__bfloat16_as_ushort(a) | ((uint32_t)__bfloat16_as_ushort(b) << 16);
}

// ---------------- split kernels ---------------------------------------------
// h/l split, vectorized by 4 floats
__global__ __launch_bounds__(256) void split_kernel(
    const float4* __restrict__ in, uint2* __restrict__ h, uint2* __restrict__ l)
{
    int i = blockIdx.x * 256 + threadIdx.x;
    float4 v = in[i];
    bf16 h0, l0, h1, l1, h2, l2, h3, l3;
    split1(v.x, h0, l0); split1(v.y, h1, l1); split1(v.z, h2, l2); split1(v.w, h3, l3);
    h[i] = make_uint2(pk2(h0, h1), pk2(h2, h3));
    l[i] = make_uint2(pk2(l0, l1), pk2(l2, l3));
}

// transpose + split: in [1024][1024] row-major (k-major), out [n][k]
__global__ __launch_bounds__(256) void tsplit_kernel(
    const float* __restrict__ in, bf16* __restrict__ oh, bf16* __restrict__ ol)
{
    __shared__ float t[32][33];
    int n0 = blockIdx.x * 32, k0 = blockIdx.y * 32;
    int x = threadIdx.x & 31, y = threadIdx.x >> 5;   // 32 x 8
    #pragma unroll
    for (int r = 0; r < 4; r++)
        t[y + 8 * r][x] = in[(long long)(k0 + y + 8 * r) * 1024 + n0 + x];
    __syncthreads();
    #pragma unroll
    for (int r = 0; r < 4; r++) {
        float v = t[x][y + 8 * r];
        bf16 h, l; split1(v, h, l);
        long long o = (long long)(n0 + y + 8 * r) * 1024 + k0 + x;
        oh[o] = h; ol[o] = l;
    }
}

// W2 bottom half: split(Y[b,t,d] * ws3[d]) -> W2h/W2l rows [512,1024)
__global__ __launch_bounds__(256) void yw_split_kernel(
    const float4* __restrict__ Y, const float4* __restrict__ ws3,
    uint2* __restrict__ W2h, uint2* __restrict__ W2l)
{
    int idx4 = blockIdx.x * 256 + threadIdx.x;   // [0, 16*512*1024/4)
    int d4 = idx4 & 255;
    int b  = idx4 >> 17;
    float4 y = Y[idx4];
    float4 w = ws3[d4];
    bf16 h0,l0,h1,l1,h2,l2,h3,l3;
    split1(y.x * w.x, h0, l0); split1(y.y * w.y, h1, l1);
    split1(y.z * w.z, h2, l2); split1(y.w * w.w, h3, l3);
    int o = idx4 + (b + 1) * 131072;
    W2h[o] = make_uint2(pk2(h0, h1), pk2(h2, h3));
    W2l[o] = make_uint2(pk2(l0, l1), pk2(l2, l3));
}

// ---------------- bf16 split NT GEMM ----------------------------------------
// C[m,n] = sum_k (Ah+Al)[m,k] * (Bh+Bl)[n,k]   (lo*lo dropped)
// EPI=0: fp32 store (+bias[n] if non-null). EPI=1: split-store bf16 into Ch/Cl.
template <int EPI>
__global__ __launch_bounds__(256, 2) void gemm_bf16_nt(
    const bf16* __restrict__ Ah, const bf16* __restrict__ Al,
    const bf16* __restrict__ Bh, const bf16* __restrict__ Bl,
    float* __restrict__ C, bf16* __restrict__ Ch, bf16* __restrict__ Cl,
    const float* __restrict__ bias,
    int K, int ldc, long long sA, long long sB, long long sC)
{
    const int bz = blockIdx.z;
    Ah += bz * sA; Al += bz * sA; Bh += bz * sB; Bl += bz * sB;

    const int m0 = blockIdx.y * 128, n0 = blockIdx.x * 128;
    const int tid = threadIdx.x, lane = tid & 31, wid = tid >> 5;
    const int wm = (wid & 1) * 64, wn = (wid >> 1) * 32;

    // [stage][0=A,1=B][128 rows * 40 bf16] (rows padded 32->40 for ldmatrix)
    __shared__ bf16 sm[2][2][128 * 40];

    float acc[4][4][4];
    #pragma unroll
    for (int i = 0; i < 4; i++)
        #pragma unroll
        for (int j = 0; j < 4; j++)
            #pragma unroll
            for (int q = 0; q < 4; q++) acc[i][j][q] = 0.f;

    // staging: 512 16B-chunks per tile (A and B each); this thread owns chunks tid, tid+256
    const int ar0 = tid >> 2,          ak0 = (tid & 3) * 8;
    const int ar1 = (tid + 256) >> 2,  ak1 = ((tid + 256) & 3) * 8;

    const int nch = (3 * K) / 32;   // k-chunks over all 3 phases

    auto issue = [&](int chunk, int stage) {
        int kk = chunk * 32;
        int phase = kk / K, kin = kk - phase * K;
        const bf16* pA = (phase == 1) ? Al : Ah;
        const bf16* pB = (phase == 2) ? Bl : Bh;
        cp16(&sm[stage][0][ar0 * 40 + ak0], pA + (long long)(m0 + ar0) * K + kin + ak0);
        cp16(&sm[stage][0][ar1 * 40 + ak1], pA + (long long)(m0 + ar1) * K + kin + ak1);
        cp16(&sm[stage][1][ar0 * 40 + ak0], pB + (long long)(n0 + ar0) * K + kin + ak0);
        cp16(&sm[stage][1][ar1 * 40 + ak1], pB + (long long)(n0 + ar1) * K + kin + ak1);
        cp_commit();
    };

    issue(0, 0);

    const int aRow = lane & 15, aKof = (lane >> 4) * 8;
    const int bRow = ((lane >> 4) << 3) + (lane & 7), bKof = ((lane >> 3) & 1) * 8;

    for (int c = 0; c < nch; c++) {
        int st = c & 1;
        if (c + 1 < nch) { issue(c + 1, st ^ 1); cp_wait<1>(); }
        else             { cp_wait<0>(); }
        __syncthreads();

        #pragma unroll
        for (int ks = 0; ks < 32; ks += 16) {
            uint32_t af[4][4];
            #pragma unroll
            for (int mt = 0; mt < 4; mt++)
                ldm_x4(af[mt], smem_u32(&sm[st][0][(wm + mt * 16 + aRow) * 40 + ks + aKof]));
            uint32_t bfr[4][4];   // bfr[bt][4]: n-frag 2*bt = regs{0,1}, 2*bt+1 = {2,3}
            #pragma unroll
            for (int bt = 0; bt < 2; bt++)
                ldm_x4(bfr[bt], smem_u32(&sm[st][1][(wn + bt * 16 + bRow) * 40 + ks + bKof]));
            #pragma unroll
            for (int mt = 0; mt < 4; mt++) {
                #pragma unroll
                for (int nt = 0; nt < 4; nt++) {
                    mma16816(acc[mt][nt], af[mt], &bfr[nt >> 1][(nt & 1) * 2]);
                }
            }
        }
        __syncthreads();
    }

    // epilogue
    const int tg = lane >> 2, tl = lane & 3;
    #pragma unroll
    for (int mt = 0; mt < 4; mt++) {
        #pragma unroll
        for (int nt = 0; nt < 4; nt++) {
            int m = m0 + wm + mt * 16 + tg;
            int n = n0 + wn + nt * 8 + 2 * tl;
            float v0 = acc[mt][nt][0], v1 = acc[mt][nt][1];
            float v2 = acc[mt][nt][2], v3 = acc[mt][nt][3];
            if (EPI == 0) {
                if (bias) { v0 += bias[n]; v1 += bias[n + 1]; v2 += bias[n]; v3 += bias[n + 1]; }
                float* Cb = C + bz * sC;
                *reinterpret_cast<float2*>(&Cb[(long long)m * ldc + n])       = make_float2(v0, v1);
                *reinterpret_cast<float2*>(&Cb[(long long)(m + 8) * ldc + n]) = make_float2(v2, v3);
            } else {
                bf16 h0,l0,h1,l1,h2,l2,h3,l3;
                split1(v0, h0, l0); split1(v1, h1, l1); split1(v2, h2, l2); split1(v3, h3, l3);
                bf16* Hb = Ch + bz * sC; bf16* Lb = Cl + bz * sC;
                *reinterpret_cast<uint32_t*>(&Hb[(long long)m * ldc + n])       = pk2(h0, h1);
                *reinterpret_cast<uint32_t*>(&Lb[(long long)m * ldc + n])       = pk2(l0, l1);
                *reinterpret_cast<uint32_t*>(&Hb[(long long)(m + 8) * ldc + n]) = pk2(h2, h3);
                *reinterpret_cast<uint32_t*>(&Lb[(long long)(m + 8) * ldc + n]) = pk2(l2, l3);
            }
        }
    }
}

// ---------------- aux kernels (fp32) ----------------------------------------
__global__ __launch_bounds__(256) void rowdot_kernel(
    const float* __restrict__ A, const float* __restrict__ v,
    const float* __restrict__ addp, float* __restrict__ out, int K)
{
    int row = blockIdx.x * 8 + (threadIdx.x >> 5);
    int lane = threadIdx.x & 31;
    const float* a = A + (long long)row * K;
    float s = 0.f;
    for (int i = lane * 4; i < K; i += 128) {
        float4 x = *reinterpret_cast<const float4*>(&a[i]);
        float4 w = *reinterpret_cast<const float4*>(&v[i]);
        s += x.x * w.x + x.y * w.y + x.z * w.z + x.w * w.w;
    }
    #pragma unroll
    for (int o = 16; o; o >>= 1) s += __shfl_xor_sync(0xffffffffu, s, o);
    if (lane == 0) out[row] = s + (addp ? addp[0] : 0.f);
}

__global__ __launch_bounds__(256) void softmax_out_kernel(
    const float* __restrict__ P, const float* __restrict__ c,
    const float* __restrict__ z, const float* __restrict__ base,
    float* __restrict__ out)
{
    const int b = blockIdx.y, r = blockIdx.x;
    const float* Prow = P + ((long long)b * RR + r) * (2 * TT);
    const float* cb = c + b * TT;
    const float* zb = z + b * TT;
    const int t = threadIdx.x;
    const int lane = t & 31, wid = t >> 5;

    float s0 = Prow[t]       + cb[t];
    float s1 = Prow[t + 256] + cb[t + 256];
    float g0 = Prow[512 + t];
    float g1 = Prow[768 + t];

    __shared__ float sm[8], smp[8], smw[8];

    float m = fmaxf(s0, s1);
    #pragma unroll
    for (int o = 16; o; o >>= 1) m = fmaxf(m, __shfl_xor_sync(0xffffffffu, m, o));
    if (lane == 0) sm[wid] = m;
    __syncthreads();
    if (wid == 0) {
        float v = sm[lane & 7];
        #pragma unroll
        for (int o = 4; o; o >>= 1) v = fmaxf(v, __shfl_xor_sync(0xffffffffu, v, o));
        if (lane == 0) sm[0] = v;
    }
    __syncthreads();
    m = sm[0];

    float p0 = expf(s0 - m), p1 = expf(s1 - m);
    float ps = p0 + p1;
    float ws = p0 * (zb[t] + g0) + p1 * (zb[t + 256] + g1);
    #pragma unroll
    for (int o = 16; o; o >>= 1) {
        ps += __shfl_xor_sync(0xffffffffu, ps, o);
        ws += __shfl_xor_sync(0xffffffffu, ws, o);
    }
    if (lane == 0) { smp[wid] = ps; smw[wid] = ws; }
    __syncthreads();
    if (t == 0) {
        float tp = 0.f, tw = 0.f;
        #pragma unroll
        for (int i = 0; i < 8; i++) { tp += smp[i]; tw += smw[i]; }
        out[b * RR + r] = base[b * RR + r] + tw / tp;
    }
}

// ---------------- launch ----------------------------------------------------
extern "C" void kernel_launch(void* const* d_in, const int* in_sizes, int n_in,
                              void* d_out, int out_size)
{
    const float* X  = (const float*)d_in[0]; // [B,R,D]
    const float* Y  = (const float*)d_in[1]; // [B,T,D]
    const float* Wr = (const float*)d_in[2]; // [D,H]
    const float* br = (const float*)d_in[3]; // [H]
    const float* Wq = (const float*)d_in[4]; // [D,H]
    const float* bq = (const float*)d_in[5]; // [H]
    const float* Ws = (const float*)d_in[6]; // [3D]
    const float* bs = (const float*)d_in[7]; // [1]
    float* out = (float*)d_out;

    float *Qp, *P, *cb, *zb, *baseb;
    bf16 *Xh, *Xl, *Yh, *Yl, *Qph, *Qpl, *WqTh, *WqTl, *Wrh, *Wrl, *W2h, *W2l;
    cudaGetSymbolAddress((void**)&Qp, g_Qp);
    cudaGetSymbolAddress((void**)&P, g_P);
    cudaGetSymbolAddress((void**)&cb, g_c);
    cudaGetSymbolAddress((void**)&zb, g_z);
    cudaGetSymbolAddress((void**)&baseb, g_base);
    cudaGetSymbolAddress((void**)&Xh, g_Xh);   cudaGetSymbolAddress((void**)&Xl, g_Xl);
    cudaGetSymbolAddress((void**)&Yh, g_Yh);   cudaGetSymbolAddress((void**)&Yl, g_Yl);
    cudaGetSymbolAddress((void**)&Qph, g_Qph); cudaGetSymbolAddress((void**)&Qpl, g_Qpl);
    cudaGetSymbolAddress((void**)&WqTh, g_WqTh); cudaGetSymbolAddress((void**)&WqTl, g_WqTl);
    cudaGetSymbolAddress((void**)&Wrh, g_Wrh); cudaGetSymbolAddress((void**)&Wrl, g_Wrl);
    cudaGetSymbolAddress((void**)&W2h, g_W2h); cudaGetSymbolAddress((void**)&W2l, g_W2l);

    // splits of inputs
    split_kernel<<<BB * RR * DD / 1024, 256>>>((const float4*)X, (uint2*)Xh, (uint2*)Xl);
    split_kernel<<<BB * TT * DD / 1024, 256>>>((const float4*)Y, (uint2*)Yh, (uint2*)Yl);
    split_kernel<<<DD * HH / 1024, 256>>>((const float4*)Wr, (uint2*)Wrh, (uint2*)Wrl);
    tsplit_kernel<<<dim3(32, 32), 256>>>(Wq, WqTh, WqTl);

    // aux vectors independent of GEMMs
    rowdot_kernel<<<(BB * TT) / 8, 256>>>(Y, Ws + DD, nullptr, zb, DD);
    rowdot_kernel<<<(BB * RR) / 8, 256>>>(X, Ws, bs, baseb, DD);
    yw_split_kernel<<<BB * TT * DD / 1024, 256>>>(
        (const float4*)Y, (const float4*)(Ws + 2 * DD), (uint2*)W2h, (uint2*)W2l);

    // GEMM1: Qp = Y @ WqT^T + bq   (M=8192, N=1024, K=1024)
    gemm_bf16_nt<0><<<dim3(8, 64, 1), 256>>>(
        Yh, Yl, WqTh, WqTl, Qp, nullptr, nullptr, bq, DD, HH, 0LL, 0LL, 0LL);

    // c[b,t] = Qp[b,t] . br ; split Qp
    rowdot_kernel<<<(BB * TT) / 8, 256>>>(Qp, br, nullptr, cb, HH);
    split_kernel<<<BB * TT * HH / 1024, 256>>>((const float4*)Qp, (uint2*)Qph, (uint2*)Qpl);

    // GEMM2: U = Qp @ Wr^T -> split-stored into W2 rows [0,512)  (per batch M=512,N=1024,K=1024)
    gemm_bf16_nt<1><<<dim3(8, 4, BB), 256>>>(
        Qph, Qpl, Wrh, Wrl, nullptr, W2h, W2l, nullptr,
        HH, DD, (long long)TT * HH, 0LL, (long long)2 * TT * DD);

    // GEMM3: P = X @ W2^T  (per batch M=1024, N=1024, K=1024)
    gemm_bf16_nt<0><<<dim3(8, 8, BB), 256>>>(
        Xh, Xl, W2h, W2l, P, nullptr, nullptr, nullptr,
        DD, 2 * TT, (long long)RR * DD, (long long)2 * TT * DD, (long long)RR * 2 * TT);

    // softmax + fused epilogue
    softmax_out_kernel<<<dim3(RR, BB), 256>>>(P, cb, zb, baseb, out);
}